// round 10
// baseline (speedup 1.0000x reference)
#include <cuda_runtime.h>
#include <cstdint>
#include <cfloat>

// VQQuantizer: approx tf32 MMA argmax + exact fp32 refinement of candidates.
// z [131072 x 64] f32, codebook [2048 x 64] f32.
// out = [codes (N*64) | indices (N) | loss (1)] f32.
// score = z.c - 0.5||c||^2 ; argmax score == argmin dist.

#define DK      64
#define MT      128
#define NT      64
#define KCODES  2048
#define TILES   (KCODES / NT)
#define THREADS 256

// hi-split codebook fragments: per tile [chunk=ks*8+nt (64)][lane(32)][{b0,b1}]
__device__ __align__(16) float g_cbh[KCODES * DK];
__device__ __align__(16) float g_cn2[KCODES];
__device__ float  g_maxcn;     // max ||c||  (atomicMax on bits; deterministic)
__device__ double g_accum;

// ---------------- helpers ----------------
__device__ __forceinline__ float tf32_rna(float x) {
    uint32_t r;
    asm("cvt.rna.tf32.f32 %0, %1;" : "=r"(r) : "f"(x));
    return __uint_as_float(r);
}
__device__ __forceinline__ void mma8(float* d, const uint32_t* a,
                                     float b0, float b1) {
    asm volatile(
        "mma.sync.aligned.m16n8k8.row.col.f32.tf32.tf32.f32 "
        "{%0,%1,%2,%3}, {%4,%5,%6,%7}, {%8,%9}, {%0,%1,%2,%3};"
        : "+f"(d[0]), "+f"(d[1]), "+f"(d[2]), "+f"(d[3])
        : "r"(a[0]), "r"(a[1]), "r"(a[2]), "r"(a[3]),
          "r"(__float_as_uint(b0)), "r"(__float_as_uint(b1)));
}
#define CP_COMMIT() asm volatile("cp.async.commit_group;" ::: "memory")
__device__ __forceinline__ void cp16(uint32_t dst, const float* src) {
    asm volatile("cp.async.cg.shared.global [%0], [%1], 16;"
                 :: "r"(dst), "l"(src) : "memory");
}

// exact fp32 score of (z row, code idx)
__device__ __forceinline__ float exact_score(const float* zrow, const float* cb, int idx) {
    const float4* zr = reinterpret_cast<const float4*>(zrow);
    const float4* cr = reinterpret_cast<const float4*>(cb + (size_t)idx * DK);
    float d = 0.f;
    #pragma unroll
    for (int u = 0; u < 16; u++) {
        float4 a = zr[u], b = cr[u];
        d += a.x * b.x + a.y * b.y + a.z * b.z + a.w * b.w;
    }
    return d - g_cn2[idx];
}

// candidate insert (smem-backed list of 4)
__device__ __forceinline__ void cand_ins(float s, int idx, float margin,
                                         float& best, int& n, int& ovf,
                                         float* csc, int* cix) {
    if (s > best - margin) {
        if (s > best) best = s;
        if (n < 4) { csc[n] = s; cix[n] = idx; n++; }
        else {
            float th = best - margin;
            int m = 0;
            #pragma unroll
            for (int i = 0; i < 4; i++) {
                float si = csc[i];
                int   ii = cix[i];
                if (si > th) { csc[m] = si; cix[m] = ii; m++; }
            }
            if (m < 4) { csc[m] = s; cix[m] = idx; m++; }
            else ovf = 1;
            n = m;
        }
    }
}

// ---------------- init kernels ----------------
__global__ void vq_pack_kernel(const float* __restrict__ cb) {
    int t = blockIdx.x * blockDim.x + threadIdx.x;   // code*64 + k
    int code = t >> 6, k = t & 63;
    float h = tf32_rna(cb[t]);
    int T  = code >> 6;
    int nt = (code & 63) >> 3, cg = code & 7;
    int ks = k >> 3, w = k & 7;
    int e  = w >> 2, tt = w & 3;
    int l  = cg * 4 + tt;
    g_cbh[(size_t)T * 4096 + (size_t)(ks * 8 + nt) * 64 + l * 2 + e] = h;
}

__global__ void vq_norm_kernel(const float* __restrict__ cb) {
    int k = blockIdx.x * blockDim.x + threadIdx.x;
    if (k == 0) g_accum = 0.0;
    if (k < KCODES) {
        const float4* r = reinterpret_cast<const float4*>(cb + (size_t)k * DK);
        float s = 0.f;
        #pragma unroll
        for (int u = 0; u < DK / 4; u++) {
            float4 v = r[u];
            s += v.x * v.x + v.y * v.y + v.z * v.z + v.w * v.w;
        }
        g_cn2[k] = 0.5f * s;
        atomicMax(reinterpret_cast<int*>(&g_maxcn), __float_as_int(sqrtf(s)));
    }
}

__global__ void vq_finish_kernel(float* __restrict__ out, int NQ) {
    out[(size_t)NQ * (DK + 1)] = (float)(g_accum / ((double)NQ * (double)DK));
}

// ---------------- main kernel ----------------
// SMEM: B 2*16KB @0 | norms 2*256 @32768 | bq @33280 | wred @33792
//       cand_sc 8KB @33824 | cand_ix 8KB @42016  -> total 50208
#define OFF_NRM  32768
#define OFF_BQ   33280
#define OFF_WRED 33792
#define OFF_CSC  33824
#define OFF_CIX  42016
#define SMEM_TOTAL 50208

__device__ __forceinline__ void issue_tile(uint32_t sb, int T, int buf, int tid) {
    const float* src = g_cbh + (size_t)T * 4096;
    #pragma unroll
    for (int r = 0; r < 4; r++) {
        int i = r * THREADS + tid;                    // 16B unit (0..1023)
        cp16(sb + buf * 16384u + (uint32_t)i * 16u, src + i * 4);
    }
    if (tid < 16) {
        cp16(sb + OFF_NRM + buf * 256u + (uint32_t)tid * 16u,
             g_cn2 + T * NT + tid * 4);
    }
}

__global__ __launch_bounds__(THREADS, 2)
void vq_main_kernel(const float* __restrict__ z,
                    const float* __restrict__ cb,
                    float* __restrict__ out, int NQ) {
    extern __shared__ char smem[];
    float* Bsm  = reinterpret_cast<float*>(smem);
    float* Nsm  = reinterpret_cast<float*>(smem + OFF_NRM);
    int*   bq   = reinterpret_cast<int*>(smem + OFF_BQ);
    float* wred = reinterpret_cast<float*>(smem + OFF_WRED);
    const uint32_t sb = (uint32_t)__cvta_generic_to_shared(smem);

    const int tid  = threadIdx.x;
    const int warp = tid >> 5, lane = tid & 31;
    const int g    = lane >> 2, tq = lane & 3;
    const int q0   = blockIdx.x * MT;

    float* csc0 = reinterpret_cast<float*>(smem + OFF_CSC) + tid * 8;
    float* csc1 = csc0 + 4;
    int*   cix0 = reinterpret_cast<int*>(smem + OFF_CIX) + tid * 8;
    int*   cix1 = cix0 + 4;

    // ---- A fragments (hi split only) + per-row |z|^2 partials ----
    uint32_t ah[32];
    float sz0 = 0.f, sz1 = 0.f;
    {
        const float* zb = z + (size_t)(q0 + warp * 16) * DK;
        #pragma unroll
        for (int ks = 0; ks < 8; ks++) {
            #pragma unroll
            for (int j = 0; j < 4; j++) {
                int row = g + (j & 1) * 8;
                int col = ks * 8 + tq + (j >> 1) * 4;
                float v = zb[row * DK + col];
                ah[ks * 4 + j] = __float_as_uint(tf32_rna(v));
                if (j & 1) sz1 += v * v; else sz0 += v * v;
            }
        }
        // quad-sum |z|^2 (lanes xor 1,2 share the same rows)
        #pragma unroll
        for (int off = 1; off <= 2; off <<= 1) {
            sz0 += __shfl_xor_sync(0xffffffffu, sz0, off);
            sz1 += __shfl_xor_sync(0xffffffffu, sz1, off);
        }
    }
    const float Mc = g_maxcn;
    const float margin0 = 2.f * (1.08e-3f * sqrtf(sz0) * Mc + 1e-3f);
    const float margin1 = 2.f * (1.08e-3f * sqrtf(sz1) * Mc + 1e-3f);

    issue_tile(sb, 0, 0, tid); CP_COMMIT();
    issue_tile(sb, 1, 1, tid); CP_COMMIT();

    float best0 = -FLT_MAX, best1 = -FLT_MAX;
    int   n0 = 0, n1 = 0, ovf0 = 0, ovf1 = 0;

    for (int T = 0; T < TILES; T++) {
        asm volatile("cp.async.wait_group 1;" ::: "memory");
        __syncthreads();

        float acc[8][4];
        #pragma unroll
        for (int nt = 0; nt < 8; nt++)
            acc[nt][0] = acc[nt][1] = acc[nt][2] = acc[nt][3] = 0.f;

        const float* Bt = Bsm + (T & 1) * 4096 + lane * 2;
        #pragma unroll
        for (int ks = 0; ks < 8; ks++) {
            #pragma unroll
            for (int nt = 0; nt < 8; nt++) {
                float2 b = *reinterpret_cast<const float2*>(Bt + (ks * 8 + nt) * 64);
                mma8(acc[nt], ah + ks * 4, b.x, b.y);
            }
        }

        const float* nrm = Nsm + (T & 1) * NT;
        #pragma unroll
        for (int nt = 0; nt < 8; nt++) {
            float2 nn = *reinterpret_cast<const float2*>(nrm + nt * 8 + 2 * tq);
            int idx = T * NT + nt * 8 + 2 * tq;
            cand_ins(acc[nt][0] - nn.x, idx,     margin0, best0, n0, ovf0, csc0, cix0);
            cand_ins(acc[nt][1] - nn.y, idx + 1, margin0, best0, n0, ovf0, csc0, cix0);
            cand_ins(acc[nt][2] - nn.x, idx,     margin1, best1, n1, ovf1, csc1, cix1);
            cand_ins(acc[nt][3] - nn.y, idx + 1, margin1, best1, n1, ovf1, csc1, cix1);
        }

        __syncthreads();
        if (T + 2 < TILES) issue_tile(sb, T + 2, T & 1, tid);
        CP_COMMIT();
    }

    // ---- exact refinement per lane, then quad arg-reduction ----
    const float* zrow0 = z + (size_t)(q0 + warp * 16 + g) * DK;
    const float* zrow1 = zrow0 + 8 * DK;

    float es0 = -FLT_MAX, es1 = -FLT_MAX;
    int   ei0 = 0x7fffffff, ei1 = 0x7fffffff;
    if (!ovf0) {
        for (int i = 0; i < n0; i++) {
            int idx = cix0[i];
            float s = exact_score(zrow0, cb, idx);
            if (s > es0 || (s == es0 && idx < ei0)) { es0 = s; ei0 = idx; }
        }
    } else {
        for (int k = 0; k < KCODES; k++) {
            float s = exact_score(zrow0, cb, k);
            if (s > es0) { es0 = s; ei0 = k; }
        }
    }
    if (!ovf1) {
        for (int i = 0; i < n1; i++) {
            int idx = cix1[i];
            float s = exact_score(zrow1, cb, idx);
            if (s > es1 || (s == es1 && idx < ei1)) { es1 = s; ei1 = idx; }
        }
    } else {
        for (int k = 0; k < KCODES; k++) {
            float s = exact_score(zrow1, cb, k);
            if (s > es1) { es1 = s; ei1 = k; }
        }
    }

    #pragma unroll
    for (int off = 1; off <= 2; off <<= 1) {
        float ob = __shfl_xor_sync(0xffffffffu, es0, off);
        int   oi = __shfl_xor_sync(0xffffffffu, ei0, off);
        if (ob > es0 || (ob == es0 && oi < ei0)) { es0 = ob; ei0 = oi; }
        ob = __shfl_xor_sync(0xffffffffu, es1, off);
        oi = __shfl_xor_sync(0xffffffffu, ei1, off);
        if (ob > es1 || (ob == es1 && oi < ei1)) { es1 = ob; ei1 = oi; }
    }
    if (tq == 0) {
        bq[warp * 16 + g]     = ei0;
        bq[warp * 16 + g + 8] = ei1;
    }
    __syncthreads();

    // ---- indices output (as float) ----
    if (tid < MT) out[(size_t)NQ * DK + q0 + tid] = (float)bq[tid];

    // ---- codes output + commit loss ----
    float ls = 0.f;
    {
        int q = tid >> 1, h = tid & 1;
        const float4* crow = reinterpret_cast<const float4*>(cb + (size_t)bq[q] * DK) + h * 8;
        const float4* zrow = reinterpret_cast<const float4*>(z + (size_t)(q0 + q) * DK) + h * 8;
        float4*       orow = reinterpret_cast<float4*>(out + (size_t)(q0 + q) * DK) + h * 8;
        #pragma unroll
        for (int u = 0; u < 8; u++) {
            float4 c = crow[u], zz = zrow[u];
            orow[u] = c;
            float dx = c.x - zz.x, dy = c.y - zz.y, dz = c.z - zz.z, dw = c.w - zz.w;
            ls += dx * dx + dy * dy + dz * dz + dw * dw;
        }
    }
    #pragma unroll
    for (int off = 16; off >= 1; off >>= 1)
        ls += __shfl_down_sync(0xffffffffu, ls, off, 32);
    if ((tid & 31) == 0) wred[tid >> 5] = ls;
    __syncthreads();
    if (tid == 0) {
        float t = 0.f;
        #pragma unroll
        for (int w = 0; w < 8; w++) t += wred[w];
        atomicAdd(&g_accum, (double)t);
    }
}

extern "C" void kernel_launch(void* const* d_in, const int* in_sizes, int n_in,
                              void* d_out, int out_size) {
    (void)n_in; (void)out_size;
    const float* z  = (const float*)d_in[0];
    const float* cb = (const float*)d_in[1];
    float* out = (float*)d_out;

    const int NQ = in_sizes[0] / DK;   // 131072

    static int attr_set = 0;
    if (!attr_set) {
        cudaFuncSetAttribute(vq_main_kernel,
                             cudaFuncAttributeMaxDynamicSharedMemorySize, SMEM_TOTAL);
        attr_set = 1;
    }

    vq_pack_kernel<<<(KCODES * DK) / 256, 256>>>(cb);
    vq_norm_kernel<<<KCODES / 128, 128>>>(cb);
    vq_main_kernel<<<NQ / MT, THREADS, SMEM_TOTAL>>>(z, cb, out, NQ);
    vq_finish_kernel<<<1, 1>>>(out, NQ);
}